// round 16
// baseline (speedup 1.0000x reference)
#include <cuda_runtime.h>
#include <math.h>

// Problem constants (match reference)
#define Wd 96
#define Hd 96
#define Dd 64
#define Ad 90
#define Ud 96
#define Vd 64
#define NSTEPS 194          // H + W + 2
#define NRAYS  (Ad * Ud)    // 8640
#define RPB    4            // rays per block in accumulate kernel

// Static device scratch (no allocations allowed).
// TRANSPOSED trace layout: g_trace[s * NRAYS + r]
//   .x = voxel base offset (i*H*D + j*D), .y = weight bits.
// A warp of 32 consecutive rays stores 256B contiguous per step (2 wavefronts
// instead of 32 scattered sectors).
__device__ int2 g_trace[NSTEPS * NRAYS];
__device__ int  g_cnt[NRAYS];

__device__ __forceinline__ void t_for(float p0, float dp, float pmin, float pmax,
                                      float& lo, float& hi) {
    const float EPS = 1e-12f;
    bool par = fabsf(dp) < EPS;
    float safe = par ? 1.0f : dp;
    float t0 = (pmin - p0) / safe;
    float t1 = (pmax - p0) / safe;
    lo = fminf(t0, t1);
    hi = fmaxf(t0, t1);
    bool inside = (p0 >= pmin) && (p0 <= pmax);
    if (par) {
        lo = inside ? -INFINITY : INFINITY;
        hi = inside ?  INFINITY : -INFINITY;
    }
}

// One thread per ray. Branchless body (R8-validated numerics), uncompacted
// stores so all lanes write step s together -> coalesced transposed store.
__global__ __launch_bounds__(64) void siddon_trace_kernel() {
    int r = blockIdx.x * blockDim.x + threadIdx.x;
    if (r >= NRAYS) return;

    const float EPS  = 1e-12f;
    const float DIAG = 1.41421356237309515f;  // f32(sqrt(2))

    int a  = r / Ud;
    int ui = r % Ud;

    const float ang_step = 3.14159274101257324f / 90.0f;
    float ang = (float)a * ang_step;
    float ct = (float)cos((double)ang);
    float st = (float)sin((double)ang);

    float u  = (float)ui - 47.5f;
    float dx = ct, dy = st;
    float x0 = -u * st;
    float y0 =  u * ct;

    const float pmin = -47.5f, pmax = 47.5f;

    float tx0, tx1, ty0, ty1;
    t_for(x0, dx, pmin, pmax, tx0, tx1);
    t_for(y0, dy, pmin, pmax, ty0, ty1);

    float t_entry = fmaxf(tx0, ty0);
    float t_exit  = fminf(tx1, ty1);
    bool  alive   = t_entry < t_exit;
    float te  = alive ? t_entry : 0.0f;
    float tex = alive ? t_exit  : 0.0f;

    float xe = x0 + te * dx;
    float ye = y0 + te * dy;

    int i = (int)fminf(fmaxf(rintf(xe + 47.5f), 0.0f), (float)(Wd - 1));
    int j = (int)fminf(fmaxf(rintf(ye + 47.5f), 0.0f), (float)(Hd - 1));

    float x = xe, y = ye, t = te;
    float wscale = DIAG / fmaxf(fabsf(dx) + fabsf(dy), EPS);

    bool okx = fabsf(dx) > EPS;
    bool oky = fabsf(dy) > EPS;
    float inv_dx = okx ? (1.0f / dx) : 0.0f;
    float inv_dy = oky ? (1.0f / dy) : 0.0f;

    float xoff = (dx > 0.0f) ? (0.5f - 47.5f) : (-0.5f - 47.5f);
    float yoff = (dy > 0.0f) ? (0.5f - 47.5f) : (-0.5f - 47.5f);
    int   istep = (dx > 0.0f) ? 1 : -1;
    int   jstep = (dy > 0.0f) ? 1 : -1;

    int nst = 0;

    #pragma unroll 1
    for (int s = 0; s < NSTEPS; s++) {
        bool valid = alive && (t < tex - EPS);

        float tx = okx ? (((float)i + xoff) - x) * inv_dx : INFINITY;
        float ty = oky ? (((float)j + yoff) - y) * inv_dy : INFINITY;

        float dt = fminf(fminf(tx, ty), tex - t);
        float w  = fmaxf(0.0f, dt * wscale);
        w = valid ? w : 0.0f;

        // Coalesced transposed store (unconditional; w=0 when invalid/tie).
        int2 e;
        e.x = i * (Hd * Dd) + j * Dd;
        e.y = __float_as_int(w);
        g_trace[s * NRAYS + r] = e;
        nst = valid ? (s + 1) : nst;

        bool cx = (tx <= ty);
        bool cy = (ty <= tx);
        int i_n = i + (cx ? istep : 0);
        int j_n = j + (cy ? jstep : 0);
        bool inb = (i_n >= 0) && (i_n < Wd) && (j_n >= 0) && (j_n < Hd);

        float dts = valid ? dt : 0.0f;
        i = valid ? i_n : i;
        j = valid ? j_n : j;
        x += dx * dts;
        y += dy * dts;
        t += dts;
        alive = valid && inb;

        if (__all_sync(0xFFFFFFFFu, !alive)) break;   // warp-uniform exit
    }
    g_cnt[r] = nst;
}

// R2-exact accum inner loop (best measured: f32, int2 smem, float2 vol loads).
// Staging reads the transposed trace block-cooperatively.
__global__ __launch_bounds__(32 * RPB) void siddon_accum_kernel(
        const float* __restrict__ vol, float* __restrict__ out) {
    __shared__ int2 s_t[RPB][NSTEPS];
    __shared__ int  s_cnt[RPB];

    int tid = threadIdx.y * 32 + threadIdx.x;
    int yy  = threadIdx.y;       // ray within block (== warp id)
    int x   = threadIdx.x;       // lane: covers v = 2x, 2x+1
    int ray0 = blockIdx.x * RPB;
    int ray  = ray0 + yy;

    if (tid < RPB)
        s_cnt[tid] = g_cnt[ray0 + tid];
    __syncthreads();

    int cmax = max(max(s_cnt[0], s_cnt[1]), max(s_cnt[2], s_cnt[3]));

    // Block-cooperative staging: entries for step n, rays ray0..ray0+3 are
    // 32B contiguous in the transposed layout.
    for (int idx = tid; idx < RPB * cmax; idx += 32 * RPB) {
        int n  = idx >> 2;       // step
        int rr = idx & 3;        // ray in block
        s_t[rr][n] = g_trace[n * NRAYS + ray0 + rr];
    }
    __syncthreads();

    int cnt = s_cnt[yy];

    const float2* vp = (const float2*)vol;
    float a0x = 0.0f, a0y = 0.0f, a1x = 0.0f, a1y = 0.0f;

    int n = 0;
    for (; n + 1 < cnt; n += 2) {
        int2 e0 = s_t[yy][n + 0];
        int2 e1 = s_t[yy][n + 1];
        float2 v0 = vp[(e0.x >> 1) + x];
        float2 v1 = vp[(e1.x >> 1) + x];
        float  w0 = __int_as_float(e0.y);
        float  w1 = __int_as_float(e1.y);
        a0x += v0.x * w0;  a0y += v0.y * w0;
        a1x += v1.x * w1;  a1y += v1.y * w1;
    }
    if (n < cnt) {
        int2 e = s_t[yy][n];
        float2 v = vp[(e.x >> 1) + x];
        float  w = __int_as_float(e.y);
        a0x += v.x * w;  a0y += v.y * w;
    }

    int a  = ray / Ud;
    int ui = ray % Ud;
    float2 res;
    res.x = a0x + a1x;
    res.y = a0y + a1y;
    // output layout (B,C,U,A,V): float2 index = (u*A + a)*32 + lane
    ((float2*)out)[(ui * Ad + a) * 32 + x] = res;
}

extern "C" void kernel_launch(void* const* d_in, const int* in_sizes, int n_in,
                              void* d_out, int out_size) {
    const float* vol = (const float*)d_in[0];
    float* out = (float*)d_out;

    siddon_trace_kernel<<<(NRAYS + 63) / 64, 64>>>();

    dim3 blk(32, RPB);                 // 128 threads
    dim3 grd(NRAYS / RPB);             // 2160 blocks
    siddon_accum_kernel<<<grd, blk>>>(vol, out);
}

// round 17
// speedup vs baseline: 1.0916x; 1.0916x over previous
#include <cuda_runtime.h>
#include <math.h>

// Problem constants (match reference)
#define Wd 96
#define Hd 96
#define Dd 64
#define Ad 90
#define Ud 96
#define Vd 64
#define NSTEPS 194          // >= max segments kx+ky+1 = 193
#define NRAYS  (Ad * Ud)    // 8640
#define RPB    4            // warps (== rays) per block

__device__ __forceinline__ void t_for(float p0, float dp, float pmin, float pmax,
                                      float& lo, float& hi) {
    const float EPS = 1e-12f;
    bool par = fabsf(dp) < EPS;
    float safe = par ? 1.0f : dp;
    float t0 = (pmin - p0) / safe;
    float t1 = (pmax - p0) / safe;
    lo = fminf(t0, t1);
    hi = fmaxf(t0, t1);
    bool inside = (p0 >= pmin) && (p0 <= pmax);
    if (par) {
        lo = inside ? -INFINITY : INFINITY;
        hi = inside ?  INFINITY : -INFINITY;
    }
}

// One warp per ray, fully fused. Phase 1: lanes compute the ray's Siddon
// segments in O(1) each (closed-form merge partition of two arithmetic
// crossing-time sequences) into smem. Phase 2: R2-exact accumulation.
__global__ __launch_bounds__(32 * RPB) void siddon_fused_kernel(
        const float* __restrict__ vol, float* __restrict__ out) {
    __shared__ int2 s_t[RPB][NSTEPS];

    int wr   = threadIdx.y;      // warp in block == ray slot
    int lane = threadIdx.x;
    int ray  = blockIdx.x * RPB + wr;

    int a  = ray / Ud;
    int ui = ray % Ud;

    const float EPS  = 1e-12f;
    const float DIAG = 1.41421356237309515f;

    // ---- per-ray setup (lane-redundant scalar math; FP64 trig lane 0 only) ----
    const float ang_step = 3.14159274101257324f / 90.0f;
    float ang = (float)a * ang_step;
    double ct_d = 0.0, st_d = 0.0;
    if (lane == 0) {
        ct_d = cos((double)ang);
        st_d = sin((double)ang);
    }
    ct_d = __shfl_sync(0xFFFFFFFFu, ct_d, 0);
    st_d = __shfl_sync(0xFFFFFFFFu, st_d, 0);
    float ct = (float)ct_d, st = (float)st_d;

    float u  = (float)ui - 47.5f;
    float dx = ct, dy = st;
    float x0 = -u * st;
    float y0 =  u * ct;

    const float pmin = -47.5f, pmax = 47.5f;
    float tx0, tx1, ty0, ty1;
    t_for(x0, dx, pmin, pmax, tx0, tx1);
    t_for(y0, dy, pmin, pmax, ty0, ty1);

    float t_entry = fmaxf(tx0, ty0);
    float t_exit  = fminf(tx1, ty1);
    bool  alive0  = t_entry < t_exit;
    float te  = alive0 ? t_entry : 0.0f;
    float tex = alive0 ? t_exit  : 0.0f;

    float xe = x0 + te * dx;
    float ye = y0 + te * dy;

    int i0 = (int)fminf(fmaxf(rintf(xe + 47.5f), 0.0f), (float)(Wd - 1));
    int j0 = (int)fminf(fmaxf(rintf(ye + 47.5f), 0.0f), (float)(Hd - 1));

    float wscale = DIAG / fmaxf(fabsf(dx) + fabsf(dy), EPS);

    bool okx = fabsf(dx) > EPS;
    bool oky = fabsf(dy) > EPS;
    float inv_dx = okx ? (1.0f / dx) : 0.0f;
    float inv_dy = oky ? (1.0f / dy) : 0.0f;

    float xoff = (dx > 0.0f) ? (0.5f - 47.5f) : (-0.5f - 47.5f);
    float yoff = (dy > 0.0f) ? (0.5f - 47.5f) : (-0.5f - 47.5f);
    int   istep = (dx > 0.0f) ? 1 : -1;
    int   jstep = (dy > 0.0f) ? 1 : -1;

    // Crossing-time sequences: TX(k)=TX0+k*dtx (k<kx), TY(l)=TY0+l*dty (l<ky)
    float TX0 = okx ? (te + (((float)i0 + xoff) - xe) * inv_dx) : INFINITY;
    float TY0 = oky ? (te + (((float)j0 + yoff) - ye) * inv_dy) : INFINITY;
    float dtx = okx ? fabsf(inv_dx) : 0.0f;
    float dty = oky ? fabsf(inv_dy) : 0.0f;

    // Closed-form crossing counts strictly before tex.
    int kx = 0;
    if (okx && TX0 < tex)
        kx = min(max((int)ceilf((tex - TX0) / dtx), 0), Wd);
    int ky = 0;
    if (oky && TY0 < tex)
        ky = min(max((int)ceilf((tex - TY0) / dty), 0), Hd);

    int nseg = alive0 ? min(kx + ky + 1, NSTEPS) : 0;

    float inv_dsum = (okx && oky) ? (1.0f / (dtx + dty)) : 0.0f;

    // ---- Phase 1: each lane computes its segments in O(1) ----
    for (int m = lane; m < nseg; m += 32) {
        int cx;
        if (!okx)      cx = 0;
        else if (!oky) cx = m;
        else {
            float q = (TY0 - TX0 + dtx + (float)m * dty) * inv_dsum;
            cx = (int)ceilf(q) - 1;
        }
        cx = min(min(cx, m), kx);
        cx = max(cx, max(0, m - ky));
        int cy = m - cx;

        float S = te;
        if (m > 0) {
            float sx = (cx > 0) ? fmaf((float)(cx - 1), dtx, TX0) : -INFINITY;
            float sy = (cy > 0) ? fmaf((float)(cy - 1), dty, TY0) : -INFINITY;
            S = fmaxf(sx, sy);
        }
        float ex = (cx < kx) ? fmaf((float)cx, dtx, TX0) : INFINITY;
        float ey = (cy < ky) ? fmaf((float)cy, dty, TY0) : INFINITY;
        float E  = fminf(fminf(ex, ey), tex);

        float w = (S < tex - EPS) ? fmaxf(0.0f, (E - S) * wscale) : 0.0f;

        int i = min(max(i0 + istep * cx, 0), Wd - 1);
        int j = min(max(j0 + jstep * cy, 0), Hd - 1);

        int2 e;
        e.x = i * (Hd * Dd) + j * Dd;
        e.y = __float_as_int(w);
        s_t[wr][m] = e;
    }
    __syncwarp();

    // ---- Phase 2: R2-exact accumulation (float2 per lane over v) ----
    const float2* vp = (const float2*)vol;
    float a0x = 0.0f, a0y = 0.0f, a1x = 0.0f, a1y = 0.0f;

    int n = 0;
    for (; n + 1 < nseg; n += 2) {
        int2 e0 = s_t[wr][n + 0];
        int2 e1 = s_t[wr][n + 1];
        float2 v0 = vp[(e0.x >> 1) + lane];
        float2 v1 = vp[(e1.x >> 1) + lane];
        float  w0 = __int_as_float(e0.y);
        float  w1 = __int_as_float(e1.y);
        a0x += v0.x * w0;  a0y += v0.y * w0;
        a1x += v1.x * w1;  a1y += v1.y * w1;
    }
    if (n < nseg) {
        int2 e = s_t[wr][n];
        float2 v = vp[(e.x >> 1) + lane];
        float  w = __int_as_float(e.y);
        a0x += v.x * w;  a0y += v.y * w;
    }

    float2 res;
    res.x = a0x + a1x;
    res.y = a0y + a1y;
    // output layout (B,C,U,A,V): float2 index = (u*A + a)*32 + lane
    ((float2*)out)[(ui * Ad + a) * 32 + lane] = res;
}

extern "C" void kernel_launch(void* const* d_in, const int* in_sizes, int n_in,
                              void* d_out, int out_size) {
    const float* vol = (const float*)d_in[0];
    float* out = (float*)d_out;

    dim3 blk(32, RPB);             // 128 threads, 4 warps = 4 rays
    dim3 grd(NRAYS / RPB);         // 2160 blocks
    siddon_fused_kernel<<<grd, blk>>>(vol, out);
}